// round 6
// baseline (speedup 1.0000x reference)
#include <cuda_runtime.h>
#include <cstdint>

// WanRotaryPosEmbedS2VStyle: build (freqs_cos, freqs_sin) grids.
//
//   output: cos (1, n_tok, 1, 128) then sin; n_tok = F*3600.
//   Per token (f,y,x): ch [0,44)=t_tab[pt], [44,86)=h_tab[y], [86,128)=w_tab[x].
//
// R6: per-thread STG path plateaued at ~14.5us, latency-bound, L2 only 47%
// (L2 store roofline ~7us). New structure: one block per (f,y) row of 60
// tokens; build cos+sin rows (2 x 30720B) in SMEM (t/h parts loaded once,
// w-lanes per token), then stream to GMEM with two 1D cp.async.bulk stores
// (async proxy / TMA path), decoupling the 81MB write stream from warp issue.

#define T_DIM 44
#define H_DIM 42
#define W_DIM 42
#define GRID_W 60
#define FIXED_REF 30

#define ROW_BYTES (GRID_W * 128 * 4)       // 30720 B per row (cos or sin)
#define SMEM_BYTES (2 * ROW_BYTES)         // 61440 B

__global__ __launch_bounds__(256)
void wan_rope_kernel(
    const float* __restrict__ tcos, const float* __restrict__ hcos,
    const float* __restrict__ wcos, const float* __restrict__ tsin,
    const float* __restrict__ hsin, const float* __restrict__ wsin,
    const int*   __restrict__ nvf_p,
    float* __restrict__ out, int n_tok)
{
    extern __shared__ float smem[];        // [0, 60*128): cos row, then sin row
    float* smc = smem;
    float* sms = smem + GRID_W * 128;

    const int b    = blockIdx.x;           // one (f,y) row
    const int f    = b / GRID_W;
    const int y    = b - f * GRID_W;
    const int wid  = threadIdx.x >> 5;
    const int lane = threadIdx.x & 31;
    const int d0   = lane << 2;            // channels [d0, d0+4)

    const int video_pp = __ldg(nvf_p);
    const int pt = (f < video_pp) ? f : FIXED_REF;

    const int tbase = pt * T_DIM;
    const int hbase = y * H_DIM - T_DIM;
    const int wbase = -(T_DIM + H_DIM);    // + x*W_DIM + d

    const float* pc[2];
    const float* ps[2];
    bool   isw[2];
    float2 cb[2], sb[2];                   // per-lane constants (t/h halves)
#pragma unroll
    for (int h = 0; h < 2; h++) {
        const int d = d0 + 2 * h;          // even; pair (d,d+1) in one table
        if (d < T_DIM)              { pc[h] = tcos + tbase + d; ps[h] = tsin + tbase + d; isw[h] = false; }
        else if (d < T_DIM + H_DIM) { pc[h] = hcos + hbase + d; ps[h] = hsin + hbase + d; isw[h] = false; }
        else                        { pc[h] = wcos + wbase + d; ps[h] = wsin + wbase + d; isw[h] = true;  }
        if (!isw[h]) {
            cb[h] = __ldg(reinterpret_cast<const float2*>(pc[h]));
            sb[h] = __ldg(reinterpret_cast<const float2*>(ps[h]));
        }
    }

    // Fill SMEM rows: warp `wid` handles tokens xi = wid, wid+8, ...
    for (int xi = wid; xi < GRID_W; xi += 8) {
        float2 c[2], s[2];
#pragma unroll
        for (int h = 0; h < 2; h++) {
            if (isw[h]) {
                c[h] = __ldg(reinterpret_cast<const float2*>(pc[h] + xi * W_DIM));
                s[h] = __ldg(reinterpret_cast<const float2*>(ps[h] + xi * W_DIM));
            } else { c[h] = cb[h]; s[h] = sb[h]; }
        }
        const int off = xi * 128 + d0;
        *reinterpret_cast<float4*>(smc + off) = make_float4(c[0].x, c[0].y, c[1].x, c[1].y);
        *reinterpret_cast<float4*>(sms + off) = make_float4(s[0].x, s[0].y, s[1].x, s[1].y);
    }

    __syncthreads();

    if (threadIdx.x == 0) {
        // Order generic-proxy STS before async-proxy bulk reads.
        asm volatile("fence.proxy.async.shared::cta;" ::: "memory");

        uint32_t sc_addr, ss_addr;
        asm("{ .reg .u64 t; cvta.to.shared.u64 t, %1; cvt.u32.u64 %0, t; }"
            : "=r"(sc_addr) : "l"(smc));
        asm("{ .reg .u64 t; cvta.to.shared.u64 t, %1; cvt.u32.u64 %0, t; }"
            : "=r"(ss_addr) : "l"(sms));

        float* gc = out + (size_t)b * (GRID_W * 128);
        float* gs = gc + (size_t)n_tok * 128;

        asm volatile(
            "cp.async.bulk.global.shared::cta.bulk_group [%0], [%1], %2;"
            :: "l"(gc), "r"(sc_addr), "n"(ROW_BYTES) : "memory");
        asm volatile(
            "cp.async.bulk.global.shared::cta.bulk_group [%0], [%1], %2;"
            :: "l"(gs), "r"(ss_addr), "n"(ROW_BYTES) : "memory");
        asm volatile("cp.async.bulk.commit_group;" ::: "memory");
        asm volatile("cp.async.bulk.wait_group 0;" ::: "memory");
    }
}

extern "C" void kernel_launch(void* const* d_in, const int* in_sizes, int n_in,
                              void* d_out, int out_size)
{
    // 0: hidden_states (unused)
    // 1: freq_t_cos  2: freq_h_cos  3: freq_w_cos
    // 4: freq_t_sin  5: freq_h_sin  6: freq_w_sin
    // 7: num_video_frames (int32)   8: num_ref_frames (int32)
    const float* tcos = (const float*)d_in[1];
    const float* hcos = (const float*)d_in[2];
    const float* wcos = (const float*)d_in[3];
    const float* tsin = (const float*)d_in[4];
    const float* hsin = (const float*)d_in[5];
    const float* wsin = (const float*)d_in[6];
    const int*   nvf  = (const int*)d_in[7];

    float* out = (float*)d_out;

    const int n_tok  = out_size / 256;     // out_size = 2 * n_tok * 128
    const int blocks = n_tok / GRID_W;     // one block per (f,y) row

    static int smem_cfgd = 0;
    if (!smem_cfgd) {
        cudaFuncSetAttribute(wan_rope_kernel,
                             cudaFuncAttributeMaxDynamicSharedMemorySize,
                             SMEM_BYTES);
        smem_cfgd = 1;
    }

    wan_rope_kernel<<<blocks, 256, SMEM_BYTES>>>(tcos, hcos, wcos, tsin, hsin,
                                                 wsin, nvf, out, n_tok);
}

// round 7
// speedup vs baseline: 1.3821x; 1.3821x over previous
#include <cuda_runtime.h>
#include <cstdint>

// WanRotaryPosEmbedS2VStyle: build (freqs_cos, freqs_sin) grids.
//
//   output: cos (1, n_tok, 1, 128) then sin; n_tok = F*3600.
//   Per token (f,y,x): ch [0,44)=t_tab[pt], [44,86)=h_tab[y], [86,128)=w_tab[x].
//
// R7: R6 (SMEM+bulk-store) regressed to 23us (occ 22%, serialized tails) —
// reverted. Best remains R3 (14.8us, per-thread STG, X_PER=4). R3's cost is
// dominated by per-warp prologue/exit across 19800 short warps plus ~1.5
// wave transitions. Now: persistent grid (888 blocks ~ 6/SM), each warp
// grid-strides over 4-token groups; nvf load + lane predicates + t/h channel
// constants hoisted out of the loop; iterations independent so loads of
// iter i+1 overlap stores of iter i.

#define T_DIM 44
#define H_DIM 42
#define W_DIM 42
#define GRID_W 60
#define GRID_HW 3600
#define FIXED_REF 30
#define X_PER 4            // tokens per work group (divides 60)

__global__ __launch_bounds__(256)
void wan_rope_kernel(
    const float* __restrict__ tcos, const float* __restrict__ hcos,
    const float* __restrict__ wcos, const float* __restrict__ tsin,
    const float* __restrict__ hsin, const float* __restrict__ wsin,
    const int*   __restrict__ nvf_p,
    float* __restrict__ out, int n_tok, int n_groups, int stride_w)
{
    const int gtid  = blockIdx.x * blockDim.x + threadIdx.x;
    const int warp0 = gtid >> 5;
    const int lane  = gtid & 31;
    const int d0    = lane << 2;           // channels [d0, d0+4)

    // ---- hoisted per-lane state (loop-invariant) ----
    const int video_pp = __ldg(nvf_p);

    // which table does each half-pair live in (per lane, fixed)
    const int dA = d0;                     // first even pair
    const int dB = d0 + 2;                 // second even pair
    const bool iswA = (dA >= T_DIM + H_DIM);
    const bool iswB = (dB >= T_DIM + H_DIM);
    const bool ishA = (dA >= T_DIM) && !iswA;
    const bool ishB = (dB >= T_DIM) && !iswB;

    for (int g = warp0; g < n_groups; g += stride_w) {
        const int tok0 = g * X_PER;
        const int f    = tok0 / GRID_HW;
        const int rem  = tok0 - f * GRID_HW;
        const int y    = rem / GRID_W;
        const int x0   = rem - y * GRID_W;

        const int pt    = (f < video_pp) ? f : FIXED_REF;
        const int tbase = pt * T_DIM;
        const int hbase = y * H_DIM - T_DIM;
        const int wbase = x0 * W_DIM - (T_DIM + H_DIM);

        const float* pcA = iswA ? (wcos + wbase + dA)
                         : ishA ? (hcos + hbase + dA) : (tcos + tbase + dA);
        const float* psA = iswA ? (wsin + wbase + dA)
                         : ishA ? (hsin + hbase + dA) : (tsin + tbase + dA);
        const float* pcB = iswB ? (wcos + wbase + dB)
                         : ishB ? (hcos + hbase + dB) : (tcos + tbase + dB);
        const float* psB = iswB ? (wsin + wbase + dB)
                         : ishB ? (hsin + hbase + dB) : (tsin + tbase + dB);

        float2 cA = __ldg(reinterpret_cast<const float2*>(pcA));
        float2 sA = __ldg(reinterpret_cast<const float2*>(psA));
        float2 cB = __ldg(reinterpret_cast<const float2*>(pcB));
        float2 sB = __ldg(reinterpret_cast<const float2*>(psB));

        float* oc = out + (size_t)tok0 * 128 + d0;
        float* os = oc + (size_t)n_tok * 128;

#pragma unroll
        for (int xi = 0; xi < X_PER; xi++) {
            if (xi) {                      // only w-lanes advance + reload
                if (iswA) {
                    pcA += W_DIM; psA += W_DIM;
                    cA = __ldg(reinterpret_cast<const float2*>(pcA));
                    sA = __ldg(reinterpret_cast<const float2*>(psA));
                }
                if (iswB) {
                    pcB += W_DIM; psB += W_DIM;
                    cB = __ldg(reinterpret_cast<const float2*>(pcB));
                    sB = __ldg(reinterpret_cast<const float2*>(psB));
                }
            }
            *reinterpret_cast<float4*>(oc + xi * 128) =
                make_float4(cA.x, cA.y, cB.x, cB.y);
            *reinterpret_cast<float4*>(os + xi * 128) =
                make_float4(sA.x, sA.y, sB.x, sB.y);
        }
    }
}

extern "C" void kernel_launch(void* const* d_in, const int* in_sizes, int n_in,
                              void* d_out, int out_size)
{
    // 0: hidden_states (unused)
    // 1: freq_t_cos  2: freq_h_cos  3: freq_w_cos
    // 4: freq_t_sin  5: freq_h_sin  6: freq_w_sin
    // 7: num_video_frames (int32)   8: num_ref_frames (int32)
    const float* tcos = (const float*)d_in[1];
    const float* hcos = (const float*)d_in[2];
    const float* wcos = (const float*)d_in[3];
    const float* tsin = (const float*)d_in[4];
    const float* hsin = (const float*)d_in[5];
    const float* wsin = (const float*)d_in[6];
    const int*   nvf  = (const int*)d_in[7];

    float* out = (float*)d_out;

    const int n_tok    = out_size / 256;   // out_size = 2 * n_tok * 128
    const int n_groups = n_tok / X_PER;    // 3600 % 4 == 0

    const int threads  = 256;              // 8 warps/block
    const int blocks   = 148 * 6;          // ~resident capacity (occ ~82% @ 29 regs)
    const int stride_w = blocks * (threads / 32);

    wan_rope_kernel<<<blocks, threads>>>(tcos, hcos, wcos, tsin, hsin, wsin,
                                         nvf, out, n_tok, n_groups, stride_w);
}